// round 14
// baseline (speedup 1.0000x reference)
#include <cuda_runtime.h>
#include <cuda_fp16.h>
#include <cstdint>

#define S    2048
#define Dm   2048
#define FF   8192
#define NH   32
#define HD   64
#define L    4096

__device__ __forceinline__ uint32_t smem_u32(const void* p) {
    uint32_t a;
    asm("{ .reg .u64 t; cvta.to.shared.u64 t, %1; cvt.u32.u64 %0, t; }" : "=r"(a) : "l"(p));
    return a;
}
__device__ __forceinline__ void ldm_x4(uint32_t* r, uint32_t a) {
    asm volatile("ldmatrix.sync.aligned.m8n8.x4.shared.b16 {%0,%1,%2,%3}, [%4];"
        : "=r"(r[0]), "=r"(r[1]), "=r"(r[2]), "=r"(r[3]) : "r"(a));
}
__device__ __forceinline__ void ldm_x4_t(uint32_t* r, uint32_t a) {
    asm volatile("ldmatrix.sync.aligned.m8n8.x4.trans.shared.b16 {%0,%1,%2,%3}, [%4];"
        : "=r"(r[0]), "=r"(r[1]), "=r"(r[2]), "=r"(r[3]) : "r"(a));
}
__device__ __forceinline__ void mma_f16(float* c, const uint32_t* a, uint32_t b0, uint32_t b1) {
    asm volatile("mma.sync.aligned.m16n8k16.row.col.f32.f16.f16.f32 "
        "{%0,%1,%2,%3}, {%4,%5,%6,%7}, {%8,%9}, {%0,%1,%2,%3};"
        : "+f"(c[0]), "+f"(c[1]), "+f"(c[2]), "+f"(c[3])
        : "r"(a[0]), "r"(a[1]), "r"(a[2]), "r"(a[3]), "r"(b0), "r"(b1));
}
__device__ __forceinline__ uint32_t pack_f16(float a, float b) {
    __half2 t; t.x = __float2half_rn(a); t.y = __float2half_rn(b);
    return *(uint32_t*)&t;
}
#define CP_ASYNC16(dst, src) \
    asm volatile("cp.async.cg.shared.global [%0], [%1], 16;" :: "r"(dst), "l"(src))
#define CP_COMMIT() asm volatile("cp.async.commit_group;" ::: "memory")
#define CP_WAIT1()  asm volatile("cp.async.wait_group 1;" ::: "memory")
#define CP_WAIT2()  asm volatile("cp.async.wait_group 2;" ::: "memory")

// ------------- scratch -------------
__device__ __half g_x  [L * Dm];
__device__ __half g_q  [S * Dm];
__device__ __half g_k  [L * Dm];
__device__ __half g_v  [L * Dm];
__device__ __half g_a  [S * Dm];
__device__ float  g_h  [S * Dm];
__device__ __half g_h2 [S * Dm];
__device__ __half g_gt [S * FF];
__device__ __half g_g  [S * FF];
__device__ __half g_wq[Dm * Dm];
__device__ __half g_wk[Dm * Dm];
__device__ __half g_wv[Dm * Dm];
__device__ __half g_wo[Dm * Dm];
__device__ __half g_wg[FF * Dm];
__device__ __half g_wu[FF * Dm];
__device__ __half g_wd[Dm * FF];

// ------------- merged fp32 -> fp16 convert of all 7 weights -------------
__global__ __launch_bounds__(256) void conv_all_kernel(
    const float* __restrict__ Wq, const float* __restrict__ Wk,
    const float* __restrict__ Wv, const float* __restrict__ Wo,
    const float* __restrict__ Wg, const float* __restrict__ Wu,
    const float* __restrict__ Wd,
    __half* __restrict__ wq, __half* __restrict__ wk, __half* __restrict__ wv,
    __half* __restrict__ wo, __half* __restrict__ wg, __half* __restrict__ wu,
    __half* __restrict__ wd)
{
    int b = blockIdx.x;
    const float* src; __half* dst; int rel;
    if      (b < 1024)  { src = Wq; dst = wq; rel = b; }
    else if (b < 2048)  { src = Wk; dst = wk; rel = b - 1024; }
    else if (b < 3072)  { src = Wv; dst = wv; rel = b - 2048; }
    else if (b < 4096)  { src = Wo; dst = wo; rel = b - 3072; }
    else if (b < 8192)  { src = Wg; dst = wg; rel = b - 4096; }
    else if (b < 12288) { src = Wu; dst = wu; rel = b - 8192; }
    else                { src = Wd; dst = wd; rel = b - 12288; }
    int base = rel * 1024 + threadIdx.x;
#pragma unroll
    for (int t = 0; t < 4; t++) {
        float4 x = ((const float4*)src)[base + t * 256];
        uint2 o; o.x = pack_f16(x.x, x.y); o.y = pack_f16(x.z, x.w);
        ((uint2*)dst)[base + t * 256] = o;
    }
}

// ------------- silu(gate) * up elementwise (fp16) -------------
__global__ __launch_bounds__(256) void mul_kernel(
    __half* __restrict__ G, const __half* __restrict__ T, int n8)
{
    int i = blockIdx.x * blockDim.x + threadIdx.x;
    if (i >= n8) return;
    uint4 a = ((const uint4*)G)[i];
    uint4 b = ((const uint4*)T)[i];
    __half2* ah = (__half2*)&a;
    __half2* bh = (__half2*)&b;
#pragma unroll
    for (int t = 0; t < 4; t++) ah[t] = __hmul2(ah[t], bh[t]);
    ((uint4*)G)[i] = a;
}

// ------------- LayerNorm -> single fp16 -------------
__global__ __launch_bounds__(256) void ln_conv_kernel(
    const float* __restrict__ X, const float* __restrict__ w,
    const float* __restrict__ b, __half* __restrict__ O)
{
    int row = blockIdx.x, tid = threadIdx.x;
    const float* xr = X + (size_t)row * Dm;
    float4 a = ((const float4*)xr)[tid * 2];
    float4 c = ((const float4*)xr)[tid * 2 + 1];
    float s  = a.x + a.y + a.z + a.w + c.x + c.y + c.z + c.w;
    float ss = a.x*a.x + a.y*a.y + a.z*a.z + a.w*a.w
             + c.x*c.x + c.y*c.y + c.z*c.z + c.w*c.w;
#pragma unroll
    for (int o = 16; o; o >>= 1) {
        s  += __shfl_xor_sync(0xffffffffu, s,  o);
        ss += __shfl_xor_sync(0xffffffffu, ss, o);
    }
    __shared__ float bs[8], bss[8];
    if ((tid & 31) == 0) { bs[tid >> 5] = s; bss[tid >> 5] = ss; }
    __syncthreads();
    float ts = 0.f, tss = 0.f;
#pragma unroll
    for (int i = 0; i < 8; i++) { ts += bs[i]; tss += bss[i]; }
    float mean = ts * (1.f / Dm);
    float inv  = rsqrtf(tss * (1.f / Dm) - mean * mean + 1e-5f);
    int d = tid * 8;
    float4 w0 = ((const float4*)w)[tid*2], w1 = ((const float4*)w)[tid*2+1];
    float4 b0 = ((const float4*)b)[tid*2], b1 = ((const float4*)b)[tid*2+1];
    float v8[8];
    v8[0]=(a.x-mean)*inv*w0.x+b0.x; v8[1]=(a.y-mean)*inv*w0.y+b0.y;
    v8[2]=(a.z-mean)*inv*w0.z+b0.z; v8[3]=(a.w-mean)*inv*w0.w+b0.w;
    v8[4]=(c.x-mean)*inv*w1.x+b1.x; v8[5]=(c.y-mean)*inv*w1.y+b1.y;
    v8[6]=(c.z-mean)*inv*w1.z+b1.z; v8[7]=(c.w-mean)*inv*w1.w+b1.w;
    uint4 o;
    o.x = pack_f16(v8[0], v8[1]); o.y = pack_f16(v8[2], v8[3]);
    o.z = pack_f16(v8[4], v8[5]); o.w = pack_f16(v8[6], v8[7]);
    *(uint4*)(O + (size_t)row * Dm + d) = o;
}

// ------------- GEMM: single fp16, 128x256 CTA tile, 8 warps (2x4) x 64x64 -------------
// MODE 0: fp32 (+Res) | 4: rope+scale -> fp16 (Q)
// MODE 7: bx<nsplit -> rope->OH (K) ; else plain->O2 (V, weights B2)
// MODE 8: bx<nsplit -> silu->OH (gate) ; else plain->O2 (up, weights B2)
#define GBK 16
#define G_ROWB 48
#define G_TILEA (128 * G_ROWB)            // 6144
#define G_TILEB (256 * G_ROWB)            // 12288
#define G_STAGEB (G_TILEA + G_TILEB)      // 18432
#define G_NST 4
#define G_DSMEM (G_NST * G_STAGEB)        // 73728

template<int MODE>
__global__ __launch_bounds__(256, 1)
void gemm1(const __half* __restrict__ A, const __half* __restrict__ B,
           const __half* __restrict__ B2, const float* __restrict__ Res,
           float* __restrict__ C, __half* __restrict__ OH,
           __half* __restrict__ O2, float scale, int M, int N, int K, int nsplit)
{
    extern __shared__ char smem[];
    uint32_t sb = smem_u32(smem);
    int tid  = threadIdx.x, wid = tid >> 5, lane = tid & 31;
    int wm = wid & 1, wn = wid >> 1;          // 2 x 4 warps, 64x64 tiles
    int bm = blockIdx.y * 128;
    int bx = blockIdx.x;
    const __half* Bp = B;
    bool first = true;
    if ((MODE == 7 || MODE == 8) && bx >= nsplit) { first = false; Bp = B2; bx -= nsplit; }
    int bn = bx * 256;

    auto loadChunk = [&](int stg, int k0) {
        uint32_t base = sb + stg * G_STAGEB;
#pragma unroll
        for (int i = 0; i < 3; i++) {
            int idx = tid + i * 256;          // 0..767
            int r = idx >> 1, c = idx & 1;
            if (r < 128) {
                CP_ASYNC16(base + r * G_ROWB + c * 16,
                           A + (size_t)(bm + r) * K + k0 + c * 8);
            } else {
                int rb = r - 128;
                CP_ASYNC16(base + G_TILEA + rb * G_ROWB + c * 16,
                           Bp + (size_t)(bn + rb) * K + k0 + c * 8);
            }
        }
    };

    float acc[4][8][4];
#pragma unroll
    for (int i = 0; i < 4; i++)
#pragma unroll
        for (int j = 0; j < 8; j++)
#pragma unroll
            for (int t = 0; t < 4; t++) acc[i][j][t] = 0.f;

    int NKC = K / GBK;
    loadChunk(0, 0);        CP_COMMIT();
    loadChunk(1, GBK);      CP_COMMIT();
    loadChunk(2, 2 * GBK);  CP_COMMIT();

    int a_row = lane & 15;
    int a_kb  = (lane >> 4) * 16;
    int b_row = lane & 7;
    int b_kb  = ((lane >> 3) & 1) * 16;
    int nsel  = (lane >> 4) & 1;

    for (int k = 0; k < NKC; k++) {
        int stg = k & (G_NST - 1);
        CP_WAIT2();
        __syncthreads();
        if (k + 3 < NKC) { loadChunk((k + 3) & (G_NST - 1), (k + 3) * GBK); }
        CP_COMMIT();
        uint32_t base = sb + stg * G_STAGEB;
        uint32_t Af[4][4];
#pragma unroll
        for (int mf = 0; mf < 4; mf++) {
            uint32_t addr = base + (uint32_t)((wm*64 + mf*16 + a_row) * G_ROWB) + a_kb;
            ldm_x4(Af[mf], addr);
        }
#pragma unroll
        for (int g = 0; g < 2; g++) {
            uint32_t Bf[4][2];
#pragma unroll
            for (int p = 0; p < 2; p++) {
                uint32_t addr = base + G_TILEA
                    + (uint32_t)((wn*64 + (g*4 + p*2 + nsel)*8 + b_row) * G_ROWB) + b_kb;
                uint32_t r4[4];
                ldm_x4(r4, addr);
                Bf[p*2][0] = r4[0]; Bf[p*2][1] = r4[1];
                Bf[p*2+1][0] = r4[2]; Bf[p*2+1][1] = r4[3];
            }
#pragma unroll
            for (int mf = 0; mf < 4; mf++)
#pragma unroll
                for (int nf = 0; nf < 4; nf++)
                    mma_f16(acc[mf][g*4 + nf], Af[mf], Bf[nf][0], Bf[nf][1]);
        }
    }

    int rr = lane >> 2, cp = lane & 3;
    if (MODE == 4 || (MODE == 7 && first)) {
#pragma unroll
        for (int mf = 0; mf < 4; mf++)
#pragma unroll
            for (int j = 0; j < 4; j++) {
                int d = cp * 2 + (j & 1);
                int row = bm + wm*64 + mf*16 + rr + ((j >> 1) * 8);
                int pos = row & (S - 1);
                float invf = __powf(10000.f, -(float)d * 0.125f);
                float sn, cs; sincosf(pos * invf, &sn, &cs);
                float x1 = acc[mf][0][j], x2 = acc[mf][1][j];
                acc[mf][0][j] = x1 * cs - x2 * sn;
                acc[mf][1][j] = x2 * cs + x1 * sn;
            }
    }
#pragma unroll
    for (int mf = 0; mf < 4; mf++) {
        int row0 = bm + wm*64 + mf*16 + rr;
#pragma unroll
        for (int nf = 0; nf < 8; nf++) {
            int col = bn + wn*64 + nf*8 + cp*2;
            float* c = acc[mf][nf];
            size_t o0 = (size_t)row0 * N + col;
            size_t o1 = (size_t)(row0 + 8) * N + col;
            if (MODE == 0) {
                float2 v0 = make_float2(c[0], c[1]);
                float2 v1 = make_float2(c[2], c[3]);
                if (Res) {
                    float2 e0 = *(const float2*)(Res + o0);
                    float2 e1 = *(const float2*)(Res + o1);
                    v0.x += e0.x; v0.y += e0.y; v1.x += e1.x; v1.y += e1.y;
                }
                *(float2*)(C + o0) = v0;
                *(float2*)(C + o1) = v1;
            } else if (MODE == 4) {
                *(uint32_t*)(OH + o0) = pack_f16(c[0] * scale, c[1] * scale);
                *(uint32_t*)(OH + o1) = pack_f16(c[2] * scale, c[3] * scale);
            } else if (MODE == 7) {
                __half* Op = first ? OH : O2;
                *(uint32_t*)(Op + o0) = pack_f16(c[0], c[1]);
                *(uint32_t*)(Op + o1) = pack_f16(c[2], c[3]);
            } else if (MODE == 8) {
                if (first) {
                    float v0 = c[0] / (1.f + __expf(-c[0]));
                    float v1 = c[1] / (1.f + __expf(-c[1]));
                    float v2 = c[2] / (1.f + __expf(-c[2]));
                    float v3 = c[3] / (1.f + __expf(-c[3]));
                    *(uint32_t*)(OH + o0) = pack_f16(v0, v1);
                    *(uint32_t*)(OH + o1) = pack_f16(v2, v3);
                } else {
                    *(uint32_t*)(O2 + o0) = pack_f16(c[0], c[1]);
                    *(uint32_t*)(O2 + o1) = pack_f16(c[2], c[3]);
                }
            }
        }
    }
}

// ------------- flash attention: fully 1-term fp16, heavy-first -------------
#define A_PITCH 144
#define A_SQ  0u
#define A_SK  9216u
#define A_SV  27648u
#define A_SMS 46080u
#define A_SLS 46336u
#define A_DSMEM 46592

__global__ __launch_bounds__(128, 2)
void attn_mma_kernel(const __half* __restrict__ Qf, const __half* __restrict__ Kf,
                     const __half* __restrict__ Vf, __half* __restrict__ O)
{
    extern __shared__ char sm[];
    uint32_t sb = smem_u32(sm);
    const int qb = gridDim.x - 1 - blockIdx.x;
    const int h = blockIdx.y;
    const int tid = threadIdx.x, wid = tid >> 5, lane = tid & 31;
    const int m0 = wid * 16;

#pragma unroll
    for (int j = 0; j < 4; j++) {
        int idx = tid + j * 128;
        int row = idx >> 3, c = idx & 7;
        size_t g = (size_t)(qb*64 + row) * Dm + h*64 + c*8;
        *(uint4*)(sm + A_SQ + row*A_PITCH + c*16) = *(const uint4*)(Qf + g);
    }
    auto loadKV = [&](int kb, int st) {
        uint32_t o = (uint32_t)st * 9216u;
#pragma unroll
        for (int j = 0; j < 4; j++) {
            int idx = tid + j * 128;
            int row = idx >> 3, c = idx & 7;
            size_t g = (size_t)(kb*64 + row) * Dm + h*64 + c*8;
            uint32_t d = o + row*A_PITCH + c*16;
            CP_ASYNC16(sb + A_SK + d, Kf + g);
            CP_ASYNC16(sb + A_SV + d, Vf + g);
        }
    };
    loadKV(0, 0); CP_COMMIT();
    __syncthreads();

    uint32_t qf[4][4];
    {
        int a_row = lane & 15, koff = (lane >> 4) * 16;
#pragma unroll
        for (int kk = 0; kk < 4; kk++) {
            uint32_t ad = sb + A_SQ + (uint32_t)(m0 + a_row) * A_PITCH + kk*32 + koff;
            ldm_x4(qf[kk], ad);
        }
    }

    float oacc[8][4];
#pragma unroll
    for (int nf = 0; nf < 8; nf++)
#pragma unroll
        for (int t = 0; t < 4; t++) oacc[nf][t] = 0.f;
    float mi0 = -1e30f, mi1 = -1e30f, li0 = 0.f, li1 = 0.f;
    const int r_l = lane >> 2, cq = (lane & 3) * 2;

    for (int kb = 0; kb <= qb; kb++) {
        if (kb < qb) loadKV(kb + 1, (kb + 1) & 1);
        CP_COMMIT();
        CP_WAIT1();
        __syncthreads();
        uint32_t st = (uint32_t)(kb & 1) * 9216u;

        float sf[8][4];
#pragma unroll
        for (int nf = 0; nf < 8; nf++)
#pragma unroll
            for (int t = 0; t < 4; t++) sf[nf][t] = 0.f;
        {
            int b_row = lane & 7, b_kb = ((lane >> 3) & 1) * 16, nsel = (lane >> 4) & 1;
#pragma unroll
            for (int kk = 0; kk < 4; kk++) {
                uint32_t bh[8][2];
#pragma unroll
                for (int g = 0; g < 2; g++)
#pragma unroll
                    for (int p = 0; p < 2; p++) {
                        uint32_t ad = sb + A_SK + st
                            + (uint32_t)(((g*4 + p*2 + nsel)*8 + b_row)) * A_PITCH
                            + kk*32 + b_kb;
                        uint32_t r4[4];
                        ldm_x4(r4, ad);
                        int f = g*4 + p*2;
                        bh[f][0] = r4[0]; bh[f][1] = r4[1];
                        bh[f+1][0] = r4[2]; bh[f+1][1] = r4[3];
                    }
#pragma unroll
                for (int nf = 0; nf < 8; nf++) mma_f16(sf[nf], qf[kk], bh[nf][0], bh[nf][1]);
            }
        }
        if (kb == qb) {
#pragma unroll
            for (int nf = 0; nf < 8; nf++)
#pragma unroll
                for (int hh = 0; hh < 2; hh++) {
                    int jl = nf*8 + cq + hh;
                    if (jl >= m0 + r_l)     sf[nf][hh]     = -1e30f;
                    if (jl >= m0 + r_l + 8) sf[nf][2 + hh] = -1e30f;
                }
        }
        float mx0 = -1e30f, mx1 = -1e30f;
#pragma unroll
        for (int nf = 0; nf < 8; nf++) {
            mx0 = fmaxf(mx0, fmaxf(sf[nf][0], sf[nf][1]));
            mx1 = fmaxf(mx1, fmaxf(sf[nf][2], sf[nf][3]));
        }
        mx0 = fmaxf(mx0, __shfl_xor_sync(0xffffffffu, mx0, 1));
        mx0 = fmaxf(mx0, __shfl_xor_sync(0xffffffffu, mx0, 2));
        mx1 = fmaxf(mx1, __shfl_xor_sync(0xffffffffu, mx1, 1));
        mx1 = fmaxf(mx1, __shfl_xor_sync(0xffffffffu, mx1, 2));
        float nm0 = fmaxf(mi0, mx0), nm1 = fmaxf(mi1, mx1);
        float sc0 = __expf(mi0 - nm0), sc1 = __expf(mi1 - nm1);
        float sum0 = 0.f, sum1 = 0.f;
#pragma unroll
        for (int nf = 0; nf < 8; nf++) {
            sf[nf][0] = (sf[nf][0] <= -1e29f) ? 0.f : __expf(sf[nf][0] - nm0); sum0 += sf[nf][0];
            sf[nf][1] = (sf[nf][1] <= -1e29f) ? 0.f : __expf(sf[nf][1] - nm0); sum0 += sf[nf][1];
            sf[nf][2] = (sf[nf][2] <= -1e29f) ? 0.f : __expf(sf[nf][2] - nm1); sum1 += sf[nf][2];
            sf[nf][3] = (sf[nf][3] <= -1e29f) ? 0.f : __expf(sf[nf][3] - nm1); sum1 += sf[nf][3];
        }
        sum0 += __shfl_xor_sync(0xffffffffu, sum0, 1);
        sum0 += __shfl_xor_sync(0xffffffffu, sum0, 2);
        sum1 += __shfl_xor_sync(0xffffffffu, sum1, 1);
        sum1 += __shfl_xor_sync(0xffffffffu, sum1, 2);
        li0 = li0 * sc0 + sum0; li1 = li1 * sc1 + sum1;
        mi0 = nm0; mi1 = nm1;
#pragma unroll
        for (int nf = 0; nf < 8; nf++) {
            oacc[nf][0] *= sc0; oacc[nf][1] *= sc0;
            oacc[nf][2] *= sc1; oacc[nf][3] *= sc1;
        }
        {
            int vrow = lane & 15, vcol = (lane >> 4) * 8;
#pragma unroll
            for (int ks = 0; ks < 4; ks++) {
                uint32_t ah[4];
                ah[0] = pack_f16(sf[2*ks][0],   sf[2*ks][1]);
                ah[1] = pack_f16(sf[2*ks][2],   sf[2*ks][3]);
                ah[2] = pack_f16(sf[2*ks+1][0], sf[2*ks+1][1]);
                ah[3] = pack_f16(sf[2*ks+1][2], sf[2*ks+1][3]);
#pragma unroll
                for (int df = 0; df < 4; df++) {
                    uint32_t v4[4];
                    uint32_t ad = sb + A_SV + st
                        + (uint32_t)(ks*16 + vrow) * A_PITCH + (df*16 + vcol) * 2;
                    ldm_x4_t(v4, ad);
                    mma_f16(oacc[2*df],     ah, v4[0], v4[1]);
                    mma_f16(oacc[2*df + 1], ah, v4[2], v4[3]);
                }
            }
        }
        __syncthreads();
    }

    float* ost = (float*)(sm + A_SK);
#pragma unroll
    for (int nf = 0; nf < 8; nf++) {
        int c = nf*8 + cq;
        ost[(m0 + r_l) * 72 + c]         = oacc[nf][0];
        ost[(m0 + r_l) * 72 + c + 1]     = oacc[nf][1];
        ost[(m0 + r_l + 8) * 72 + c]     = oacc[nf][2];
        ost[(m0 + r_l + 8) * 72 + c + 1] = oacc[nf][3];
    }
    if ((lane & 3) == 0) {
        ((float*)(sm + A_SMS))[m0 + r_l]     = mi0;
        ((float*)(sm + A_SMS))[m0 + r_l + 8] = mi1;
        ((float*)(sm + A_SLS))[m0 + r_l]     = li0;
        ((float*)(sm + A_SLS))[m0 + r_l + 8] = li1;
    }
    __syncthreads();

    {
        int m = tid >> 1, hf = tid & 1;
        int i = qb*64 + m;
        const __half2* q2 = (const __half2*)(Qf + (size_t)i * Dm + h*64);
        const __half2* k2 = (const __half2*)(Kf + (size_t)(S + i) * Dm + h*64);
        float dot = 0.f;
#pragma unroll
        for (int t = 0; t < 32; t++) {
            float2 qa = __half22float2(q2[t]);
            float2 ka = __half22float2(k2[t]);
            dot += qa.x * ka.x + qa.y * ka.y;
        }
        float ssf = dot;
        float mi = ((float*)(sm + A_SMS))[m];
        float li = ((float*)(sm + A_SLS))[m];
        float nm = fmaxf(mi, ssf);
        float sc = __expf(mi - nm);
        float pp = __expf(ssf - nm);
        float inv = 1.f / (li * sc + pp);
        const __half2* v2 = (const __half2*)(Vf + (size_t)(S + i) * Dm + h*64 + hf*32);
        float* orow = ost + m*72 + hf*32;
        uint32_t hh[8];
#pragma unroll
        for (int t = 0; t < 16; t++) {
            float2 va = __half22float2(v2[t]);
            float val0 = (orow[t*2]   * sc + pp * va.x) * inv;
            float val1 = (orow[t*2+1] * sc + pp * va.y) * inv;
            hh[t & 7] = pack_f16(val0, val1);
            if ((t & 7) == 7) {
                int t8 = t >> 3;
                *(uint4*)(O + (size_t)i * Dm + h*64 + hf*32 + t8*16)     = *(uint4*)(hh);
                *(uint4*)(O + (size_t)i * Dm + h*64 + hf*32 + t8*16 + 8) = *(uint4*)(hh + 4);
            }
        }
    }
}

// ------------- launch -------------
extern "C" void kernel_launch(void* const* d_in, const int* in_sizes, int n_in,
                              void* d_out, int out_size)
{
    const float* hidden = (const float*)d_in[0];
    const float* memory = (const float*)d_in[1];
    const float* ln1w = (const float*)d_in[4];
    const float* ln1b = (const float*)d_in[5];
    const float* ln2w = (const float*)d_in[6];
    const float* ln2b = (const float*)d_in[7];
    const float* Wq = (const float*)d_in[8];
    const float* Wk = (const float*)d_in[9];
    const float* Wv = (const float*)d_in[10];
    const float* Wo = (const float*)d_in[11];
    const float* Wg = (const float*)d_in[12];
    const float* Wu = (const float*)d_in[13];
    const float* Wd = (const float*)d_in[14];
    float* out = (float*)d_out;

    void* p;
    cudaGetSymbolAddress(&p, g_x);   __half* x = (__half*)p;
    cudaGetSymbolAddress(&p, g_q);   __half* q = (__half*)p;
    cudaGetSymbolAddress(&p, g_k);   __half* k = (__half*)p;
    cudaGetSymbolAddress(&p, g_v);   __half* v = (__half*)p;
    cudaGetSymbolAddress(&p, g_a);   __half* a = (__half*)p;
    cudaGetSymbolAddress(&p, g_h);   float* hbuf = (float*)p;
    cudaGetSymbolAddress(&p, g_h2);  __half* h2 = (__half*)p;
    cudaGetSymbolAddress(&p, g_gt);  __half* gt = (__half*)p;
    cudaGetSymbolAddress(&p, g_g);   __half* gbuf = (__half*)p;
    cudaGetSymbolAddress(&p, g_wq);  __half* wq = (__half*)p;
    cudaGetSymbolAddress(&p, g_wk);  __half* wk = (__half*)p;
    cudaGetSymbolAddress(&p, g_wv);  __half* wv = (__half*)p;
    cudaGetSymbolAddress(&p, g_wo);  __half* wo = (__half*)p;
    cudaGetSymbolAddress(&p, g_wg);  __half* wg = (__half*)p;
    cudaGetSymbolAddress(&p, g_wu);  __half* wu = (__half*)p;
    cudaGetSymbolAddress(&p, g_wd);  __half* wd = (__half*)p;

    cudaFuncSetAttribute(gemm1<0>, cudaFuncAttributeMaxDynamicSharedMemorySize, G_DSMEM);
    cudaFuncSetAttribute(gemm1<4>, cudaFuncAttributeMaxDynamicSharedMemorySize, G_DSMEM);
    cudaFuncSetAttribute(gemm1<7>, cudaFuncAttributeMaxDynamicSharedMemorySize, G_DSMEM);
    cudaFuncSetAttribute(gemm1<8>, cudaFuncAttributeMaxDynamicSharedMemorySize, G_DSMEM);
    cudaFuncSetAttribute(attn_mma_kernel, cudaFuncAttributeMaxDynamicSharedMemorySize, A_DSMEM);

    ln_conv_kernel<<<S, 256>>>(memory, ln1w, ln1b, x);
    ln_conv_kernel<<<S, 256>>>(hidden, ln1w, ln1b, x + (size_t)S * Dm);

    conv_all_kernel<<<16384, 256>>>(Wq, Wk, Wv, Wo, Wg, Wu, Wd,
                                    wq, wk, wv, wo, wg, wu, wd);

    {
        // K + V merged: 16 x 32 grid of 128x256 tiles
        dim3 gKV(16, L / 128);
        gemm1<7><<<gKV, 256, G_DSMEM>>>(x, wk, wv, nullptr, nullptr, k, v,
                                        1.0f, L, Dm, Dm, 8);
        dim3 gQ(8, S / 128);
        gemm1<4><<<gQ, 256, G_DSMEM>>>(x + (size_t)S * Dm, wq, nullptr, nullptr, nullptr,
                                       q, nullptr, 0.125f, S, Dm, Dm, 0);
    }

    {
        dim3 g(S / 64, NH);
        attn_mma_kernel<<<g, 128, A_DSMEM>>>(q, k, v, a);
    }

    {
        dim3 g(Dm / 256, S / 128);
        gemm1<0><<<g, 256, G_DSMEM>>>(a, wo, nullptr, hidden, hbuf, nullptr, nullptr,
                                      1.0f, S, Dm, Dm, 0);
    }
    ln_conv_kernel<<<S, 256>>>(hbuf, ln2w, ln2b, h2);
    {
        // gate + up merged: 64 x 16 grid
        dim3 g(64, S / 128);
        gemm1<8><<<g, 256, G_DSMEM>>>(h2, wg, wu, nullptr, nullptr, gt, gbuf,
                                      1.0f, S, FF, Dm, 32);
        mul_kernel<<<S * FF / 2048, 256>>>(gbuf, gt, S * FF / 8);
    }
    {
        dim3 g(Dm / 256, S / 128);
        gemm1<0><<<g, 256, G_DSMEM>>>(gbuf, wd, nullptr, hbuf, out, nullptr, nullptr,
                                      1.0f, S, Dm, FF, 0);
    }
}

// round 15
// speedup vs baseline: 1.3887x; 1.3887x over previous
#include <cuda_runtime.h>
#include <cuda_fp16.h>
#include <cstdint>

#define S    2048
#define Dm   2048
#define FF   8192
#define NH   32
#define HD   64
#define L    4096

__device__ __forceinline__ uint32_t smem_u32(const void* p) {
    uint32_t a;
    asm("{ .reg .u64 t; cvta.to.shared.u64 t, %1; cvt.u32.u64 %0, t; }" : "=r"(a) : "l"(p));
    return a;
}
__device__ __forceinline__ void ldm_x4(uint32_t* r, uint32_t a) {
    asm volatile("ldmatrix.sync.aligned.m8n8.x4.shared.b16 {%0,%1,%2,%3}, [%4];"
        : "=r"(r[0]), "=r"(r[1]), "=r"(r[2]), "=r"(r[3]) : "r"(a));
}
__device__ __forceinline__ void ldm_x4_t(uint32_t* r, uint32_t a) {
    asm volatile("ldmatrix.sync.aligned.m8n8.x4.trans.shared.b16 {%0,%1,%2,%3}, [%4];"
        : "=r"(r[0]), "=r"(r[1]), "=r"(r[2]), "=r"(r[3]) : "r"(a));
}
__device__ __forceinline__ void mma_f16(float* c, const uint32_t* a, uint32_t b0, uint32_t b1) {
    asm volatile("mma.sync.aligned.m16n8k16.row.col.f32.f16.f16.f32 "
        "{%0,%1,%2,%3}, {%4,%5,%6,%7}, {%8,%9}, {%0,%1,%2,%3};"
        : "+f"(c[0]), "+f"(c[1]), "+f"(c[2]), "+f"(c[3])
        : "r"(a[0]), "r"(a[1]), "r"(a[2]), "r"(a[3]), "r"(b0), "r"(b1));
}
__device__ __forceinline__ uint32_t pack_f16(float a, float b) {
    __half2 t; t.x = __float2half_rn(a); t.y = __float2half_rn(b);
    return *(uint32_t*)&t;
}
#define CP_ASYNC16(dst, src) \
    asm volatile("cp.async.cg.shared.global [%0], [%1], 16;" :: "r"(dst), "l"(src))
#define CP_COMMIT() asm volatile("cp.async.commit_group;" ::: "memory")
#define CP_WAIT1()  asm volatile("cp.async.wait_group 1;" ::: "memory")
#define CP_WAIT2()  asm volatile("cp.async.wait_group 2;" ::: "memory")

// ------------- scratch -------------
__device__ __half g_x  [L * Dm];
__device__ __half g_q  [S * Dm];
__device__ __half g_k  [L * Dm];
__device__ __half g_v  [L * Dm];
__device__ __half g_a  [S * Dm];
__device__ float  g_h  [S * Dm];
__device__ __half g_h2 [S * Dm];
__device__ __half g_gt [S * FF];
__device__ __half g_g  [S * FF];
__device__ __half g_wq[Dm * Dm];
__device__ __half g_wk[Dm * Dm];
__device__ __half g_wv[Dm * Dm];
__device__ __half g_wo[Dm * Dm];
__device__ __half g_wg[FF * Dm];
__device__ __half g_wu[FF * Dm];
__device__ __half g_wd[Dm * FF];

// ------------- merged fp32 -> fp16 convert of all 7 weights -------------
__global__ __launch_bounds__(256) void conv_all_kernel(
    const float* __restrict__ Wq, const float* __restrict__ Wk,
    const float* __restrict__ Wv, const float* __restrict__ Wo,
    const float* __restrict__ Wg, const float* __restrict__ Wu,
    const float* __restrict__ Wd,
    __half* __restrict__ wq, __half* __restrict__ wk, __half* __restrict__ wv,
    __half* __restrict__ wo, __half* __restrict__ wg, __half* __restrict__ wu,
    __half* __restrict__ wd)
{
    int b = blockIdx.x;
    const float* src; __half* dst; int rel;
    if      (b < 1024)  { src = Wq; dst = wq; rel = b; }
    else if (b < 2048)  { src = Wk; dst = wk; rel = b - 1024; }
    else if (b < 3072)  { src = Wv; dst = wv; rel = b - 2048; }
    else if (b < 4096)  { src = Wo; dst = wo; rel = b - 3072; }
    else if (b < 8192)  { src = Wg; dst = wg; rel = b - 4096; }
    else if (b < 12288) { src = Wu; dst = wu; rel = b - 8192; }
    else                { src = Wd; dst = wd; rel = b - 12288; }
    int base = rel * 1024 + threadIdx.x;
#pragma unroll
    for (int t = 0; t < 4; t++) {
        float4 x = ((const float4*)src)[base + t * 256];
        uint2 o; o.x = pack_f16(x.x, x.y); o.y = pack_f16(x.z, x.w);
        ((uint2*)dst)[base + t * 256] = o;
    }
}

// ------------- silu(gate) * up elementwise (fp16) -------------
__global__ __launch_bounds__(256) void mul_kernel(
    __half* __restrict__ G, const __half* __restrict__ T, int n8)
{
    int i = blockIdx.x * blockDim.x + threadIdx.x;
    if (i >= n8) return;
    uint4 a = ((const uint4*)G)[i];
    uint4 b = ((const uint4*)T)[i];
    __half2* ah = (__half2*)&a;
    __half2* bh = (__half2*)&b;
#pragma unroll
    for (int t = 0; t < 4; t++) ah[t] = __hmul2(ah[t], bh[t]);
    ((uint4*)G)[i] = a;
}

// ------------- LayerNorm -> single fp16 -------------
__global__ __launch_bounds__(256) void ln_conv_kernel(
    const float* __restrict__ X, const float* __restrict__ w,
    const float* __restrict__ b, __half* __restrict__ O)
{
    int row = blockIdx.x, tid = threadIdx.x;
    const float* xr = X + (size_t)row * Dm;
    float4 a = ((const float4*)xr)[tid * 2];
    float4 c = ((const float4*)xr)[tid * 2 + 1];
    float s  = a.x + a.y + a.z + a.w + c.x + c.y + c.z + c.w;
    float ss = a.x*a.x + a.y*a.y + a.z*a.z + a.w*a.w
             + c.x*c.x + c.y*c.y + c.z*c.z + c.w*c.w;
#pragma unroll
    for (int o = 16; o; o >>= 1) {
        s  += __shfl_xor_sync(0xffffffffu, s,  o);
        ss += __shfl_xor_sync(0xffffffffu, ss, o);
    }
    __shared__ float bs[8], bss[8];
    if ((tid & 31) == 0) { bs[tid >> 5] = s; bss[tid >> 5] = ss; }
    __syncthreads();
    float ts = 0.f, tss = 0.f;
#pragma unroll
    for (int i = 0; i < 8; i++) { ts += bs[i]; tss += bss[i]; }
    float mean = ts * (1.f / Dm);
    float inv  = rsqrtf(tss * (1.f / Dm) - mean * mean + 1e-5f);
    int d = tid * 8;
    float4 w0 = ((const float4*)w)[tid*2], w1 = ((const float4*)w)[tid*2+1];
    float4 b0 = ((const float4*)b)[tid*2], b1 = ((const float4*)b)[tid*2+1];
    float v8[8];
    v8[0]=(a.x-mean)*inv*w0.x+b0.x; v8[1]=(a.y-mean)*inv*w0.y+b0.y;
    v8[2]=(a.z-mean)*inv*w0.z+b0.z; v8[3]=(a.w-mean)*inv*w0.w+b0.w;
    v8[4]=(c.x-mean)*inv*w1.x+b1.x; v8[5]=(c.y-mean)*inv*w1.y+b1.y;
    v8[6]=(c.z-mean)*inv*w1.z+b1.z; v8[7]=(c.w-mean)*inv*w1.w+b1.w;
    uint4 o;
    o.x = pack_f16(v8[0], v8[1]); o.y = pack_f16(v8[2], v8[3]);
    o.z = pack_f16(v8[4], v8[5]); o.w = pack_f16(v8[6], v8[7]);
    *(uint4*)(O + (size_t)row * Dm + d) = o;
}

// ------------- GEMM: fp16, 128x128 CTA, 4 warps x 64x64, GBK=32, 2 CTAs/SM -------------
// MODE 0: fp32 (+Res) | 4: rope+scale -> fp16 (Q)
// MODE 7: bx<nsplit -> rope->OH (K) ; else plain->O2 (V, weights B2)
// MODE 8: bx<nsplit -> silu->OH (gate) ; else plain->O2 (up, weights B2)
#define GBK 32
#define G_ROWB 80
#define G_TILEB (128 * G_ROWB)            // 10240
#define G_STAGEB (2 * G_TILEB)            // 20480 (A, B)
#define G_NST 4
#define G_DSMEM (G_NST * G_STAGEB)        // 81920

template<int MODE>
__global__ __launch_bounds__(128, 2)
void gemm1(const __half* __restrict__ A, const __half* __restrict__ B,
           const __half* __restrict__ B2, const float* __restrict__ Res,
           float* __restrict__ C, __half* __restrict__ OH,
           __half* __restrict__ O2, float scale, int M, int N, int K, int nsplit)
{
    extern __shared__ char smem[];
    uint32_t sb = smem_u32(smem);
    int tid  = threadIdx.x, wid = tid >> 5, lane = tid & 31;
    int wm = wid & 1, wn = wid >> 1;
    int bm = blockIdx.y * 128;
    int bx = blockIdx.x;
    const __half* Bp = B;
    bool first = true;
    if ((MODE == 7 || MODE == 8) && bx >= nsplit) { first = false; Bp = B2; bx -= nsplit; }
    int bn = bx * 128;

    auto loadChunk = [&](int stg, int k0) {
        uint32_t base = sb + stg * G_STAGEB;
#pragma unroll
        for (int i = 0; i < 4; i++) {
            int idx = tid + i * 128;          // 0..511
            int r = idx >> 2, c = idx & 3;
            uint32_t doff = r * G_ROWB + c * 16;
            size_t soff = (size_t)r * K + k0 + c * 8;
            CP_ASYNC16(base + doff,           A  + (size_t)bm * K + soff);
            CP_ASYNC16(base + G_TILEB + doff, Bp + (size_t)bn * K + soff);
        }
    };

    float acc[4][8][4];
#pragma unroll
    for (int i = 0; i < 4; i++)
#pragma unroll
        for (int j = 0; j < 8; j++)
#pragma unroll
            for (int t = 0; t < 4; t++) acc[i][j][t] = 0.f;

    int NKC = K / GBK;
    loadChunk(0, 0);        CP_COMMIT();
    loadChunk(1, GBK);      CP_COMMIT();
    loadChunk(2, 2 * GBK);  CP_COMMIT();

    int a_row = lane & 15;
    int a_kb  = (lane >> 4) * 16;
    int b_row = lane & 7;
    int b_kb  = ((lane >> 3) & 1) * 16;
    int nsel  = (lane >> 4) & 1;

    for (int k = 0; k < NKC; k++) {
        int stg = k & (G_NST - 1);
        CP_WAIT2();
        __syncthreads();
        if (k + 3 < NKC) { loadChunk((k + 3) & (G_NST - 1), (k + 3) * GBK); }
        CP_COMMIT();
        uint32_t base = sb + stg * G_STAGEB;
#pragma unroll
        for (int kk = 0; kk < 2; kk++) {
            uint32_t Af[4][4];
#pragma unroll
            for (int mf = 0; mf < 4; mf++) {
                uint32_t addr = base + (uint32_t)((wm*64 + mf*16 + a_row) * G_ROWB)
                              + kk*32 + a_kb;
                ldm_x4(Af[mf], addr);
            }
#pragma unroll
            for (int g = 0; g < 2; g++) {
                uint32_t Bf[4][2];
#pragma unroll
                for (int p = 0; p < 2; p++) {
                    uint32_t addr = base + G_TILEB
                        + (uint32_t)((wn*64 + (g*4 + p*2 + nsel)*8 + b_row) * G_ROWB)
                        + kk*32 + b_kb;
                    uint32_t r4[4];
                    ldm_x4(r4, addr);
                    Bf[p*2][0] = r4[0]; Bf[p*2][1] = r4[1];
                    Bf[p*2+1][0] = r4[2]; Bf[p*2+1][1] = r4[3];
                }
#pragma unroll
                for (int mf = 0; mf < 4; mf++)
#pragma unroll
                    for (int nf = 0; nf < 4; nf++)
                        mma_f16(acc[mf][g*4 + nf], Af[mf], Bf[nf][0], Bf[nf][1]);
            }
        }
    }

    int rr = lane >> 2, cp = lane & 3;
    if (MODE == 4 || (MODE == 7 && first)) {
#pragma unroll
        for (int mf = 0; mf < 4; mf++)
#pragma unroll
            for (int j = 0; j < 4; j++) {
                int d = cp * 2 + (j & 1);
                int row = bm + wm*64 + mf*16 + rr + ((j >> 1) * 8);
                int pos = row & (S - 1);
                float invf = __powf(10000.f, -(float)d * 0.125f);
                float sn, cs; sincosf(pos * invf, &sn, &cs);
                float x1 = acc[mf][0][j], x2 = acc[mf][1][j];
                acc[mf][0][j] = x1 * cs - x2 * sn;
                acc[mf][1][j] = x2 * cs + x1 * sn;
            }
    }
#pragma unroll
    for (int mf = 0; mf < 4; mf++) {
        int row0 = bm + wm*64 + mf*16 + rr;
#pragma unroll
        for (int nf = 0; nf < 8; nf++) {
            int col = bn + wn*64 + nf*8 + cp*2;
            float* c = acc[mf][nf];
            size_t o0 = (size_t)row0 * N + col;
            size_t o1 = (size_t)(row0 + 8) * N + col;
            if (MODE == 0) {
                float2 v0 = make_float2(c[0], c[1]);
                float2 v1 = make_float2(c[2], c[3]);
                if (Res) {
                    float2 e0 = *(const float2*)(Res + o0);
                    float2 e1 = *(const float2*)(Res + o1);
                    v0.x += e0.x; v0.y += e0.y; v1.x += e1.x; v1.y += e1.y;
                }
                *(float2*)(C + o0) = v0;
                *(float2*)(C + o1) = v1;
            } else if (MODE == 4) {
                *(uint32_t*)(OH + o0) = pack_f16(c[0] * scale, c[1] * scale);
                *(uint32_t*)(OH + o1) = pack_f16(c[2] * scale, c[3] * scale);
            } else if (MODE == 7) {
                __half* Op = first ? OH : O2;
                *(uint32_t*)(Op + o0) = pack_f16(c[0], c[1]);
                *(uint32_t*)(Op + o1) = pack_f16(c[2], c[3]);
            } else if (MODE == 8) {
                if (first) {
                    float v0 = c[0] / (1.f + __expf(-c[0]));
                    float v1 = c[1] / (1.f + __expf(-c[1]));
                    float v2 = c[2] / (1.f + __expf(-c[2]));
                    float v3 = c[3] / (1.f + __expf(-c[3]));
                    *(uint32_t*)(OH + o0) = pack_f16(v0, v1);
                    *(uint32_t*)(OH + o1) = pack_f16(v2, v3);
                } else {
                    *(uint32_t*)(O2 + o0) = pack_f16(c[0], c[1]);
                    *(uint32_t*)(O2 + o1) = pack_f16(c[2], c[3]);
                }
            }
        }
    }
}

// ------------- flash attention: fully 1-term fp16, heavy-first -------------
#define A_PITCH 144
#define A_SQ  0u
#define A_SK  9216u
#define A_SV  27648u
#define A_SMS 46080u
#define A_SLS 46336u
#define A_DSMEM 46592

__global__ __launch_bounds__(128, 2)
void attn_mma_kernel(const __half* __restrict__ Qf, const __half* __restrict__ Kf,
                     const __half* __restrict__ Vf, __half* __restrict__ O)
{
    extern __shared__ char sm[];
    uint32_t sb = smem_u32(sm);
    const int qb = gridDim.x - 1 - blockIdx.x;
    const int h = blockIdx.y;
    const int tid = threadIdx.x, wid = tid >> 5, lane = tid & 31;
    const int m0 = wid * 16;

#pragma unroll
    for (int j = 0; j < 4; j++) {
        int idx = tid + j * 128;
        int row = idx >> 3, c = idx & 7;
        size_t g = (size_t)(qb*64 + row) * Dm + h*64 + c*8;
        *(uint4*)(sm + A_SQ + row*A_PITCH + c*16) = *(const uint4*)(Qf + g);
    }
    auto loadKV = [&](int kb, int st) {
        uint32_t o = (uint32_t)st * 9216u;
#pragma unroll
        for (int j = 0; j < 4; j++) {
            int idx = tid + j * 128;
            int row = idx >> 3, c = idx & 7;
            size_t g = (size_t)(kb*64 + row) * Dm + h*64 + c*8;
            uint32_t d = o + row*A_PITCH + c*16;
            CP_ASYNC16(sb + A_SK + d, Kf + g);
            CP_ASYNC16(sb + A_SV + d, Vf + g);
        }
    };
    loadKV(0, 0); CP_COMMIT();
    __syncthreads();

    uint32_t qf[4][4];
    {
        int a_row = lane & 15, koff = (lane >> 4) * 16;
#pragma unroll
        for (int kk = 0; kk < 4; kk++) {
            uint32_t ad = sb + A_SQ + (uint32_t)(m0 + a_row) * A_PITCH + kk*32 + koff;
            ldm_x4(qf[kk], ad);
        }
    }

    float oacc[8][4];
#pragma unroll
    for (int nf = 0; nf < 8; nf++)
#pragma unroll
        for (int t = 0; t < 4; t++) oacc[nf][t] = 0.f;
    float mi0 = -1e30f, mi1 = -1e30f, li0 = 0.f, li1 = 0.f;
    const int r_l = lane >> 2, cq = (lane & 3) * 2;

    for (int kb = 0; kb <= qb; kb++) {
        if (kb < qb) loadKV(kb + 1, (kb + 1) & 1);
        CP_COMMIT();
        CP_WAIT1();
        __syncthreads();
        uint32_t st = (uint32_t)(kb & 1) * 9216u;

        float sf[8][4];
#pragma unroll
        for (int nf = 0; nf < 8; nf++)
#pragma unroll
            for (int t = 0; t < 4; t++) sf[nf][t] = 0.f;
        {
            int b_row = lane & 7, b_kb = ((lane >> 3) & 1) * 16, nsel = (lane >> 4) & 1;
#pragma unroll
            for (int kk = 0; kk < 4; kk++) {
                uint32_t bh[8][2];
#pragma unroll
                for (int g = 0; g < 2; g++)
#pragma unroll
                    for (int p = 0; p < 2; p++) {
                        uint32_t ad = sb + A_SK + st
                            + (uint32_t)(((g*4 + p*2 + nsel)*8 + b_row)) * A_PITCH
                            + kk*32 + b_kb;
                        uint32_t r4[4];
                        ldm_x4(r4, ad);
                        int f = g*4 + p*2;
                        bh[f][0] = r4[0]; bh[f][1] = r4[1];
                        bh[f+1][0] = r4[2]; bh[f+1][1] = r4[3];
                    }
#pragma unroll
                for (int nf = 0; nf < 8; nf++) mma_f16(sf[nf], qf[kk], bh[nf][0], bh[nf][1]);
            }
        }
        if (kb == qb) {
#pragma unroll
            for (int nf = 0; nf < 8; nf++)
#pragma unroll
                for (int hh = 0; hh < 2; hh++) {
                    int jl = nf*8 + cq + hh;
                    if (jl >= m0 + r_l)     sf[nf][hh]     = -1e30f;
                    if (jl >= m0 + r_l + 8) sf[nf][2 + hh] = -1e30f;
                }
        }
        float mx0 = -1e30f, mx1 = -1e30f;
#pragma unroll
        for (int nf = 0; nf < 8; nf++) {
            mx0 = fmaxf(mx0, fmaxf(sf[nf][0], sf[nf][1]));
            mx1 = fmaxf(mx1, fmaxf(sf[nf][2], sf[nf][3]));
        }
        mx0 = fmaxf(mx0, __shfl_xor_sync(0xffffffffu, mx0, 1));
        mx0 = fmaxf(mx0, __shfl_xor_sync(0xffffffffu, mx0, 2));
        mx1 = fmaxf(mx1, __shfl_xor_sync(0xffffffffu, mx1, 1));
        mx1 = fmaxf(mx1, __shfl_xor_sync(0xffffffffu, mx1, 2));
        float nm0 = fmaxf(mi0, mx0), nm1 = fmaxf(mi1, mx1);
        float sc0 = __expf(mi0 - nm0), sc1 = __expf(mi1 - nm1);
        float sum0 = 0.f, sum1 = 0.f;
#pragma unroll
        for (int nf = 0; nf < 8; nf++) {
            sf[nf][0] = (sf[nf][0] <= -1e29f) ? 0.f : __expf(sf[nf][0] - nm0); sum0 += sf[nf][0];
            sf[nf][1] = (sf[nf][1] <= -1e29f) ? 0.f : __expf(sf[nf][1] - nm0); sum0 += sf[nf][1];
            sf[nf][2] = (sf[nf][2] <= -1e29f) ? 0.f : __expf(sf[nf][2] - nm1); sum1 += sf[nf][2];
            sf[nf][3] = (sf[nf][3] <= -1e29f) ? 0.f : __expf(sf[nf][3] - nm1); sum1 += sf[nf][3];
        }
        sum0 += __shfl_xor_sync(0xffffffffu, sum0, 1);
        sum0 += __shfl_xor_sync(0xffffffffu, sum0, 2);
        sum1 += __shfl_xor_sync(0xffffffffu, sum1, 1);
        sum1 += __shfl_xor_sync(0xffffffffu, sum1, 2);
        li0 = li0 * sc0 + sum0; li1 = li1 * sc1 + sum1;
        mi0 = nm0; mi1 = nm1;
#pragma unroll
        for (int nf = 0; nf < 8; nf++) {
            oacc[nf][0] *= sc0; oacc[nf][1] *= sc0;
            oacc[nf][2] *= sc1; oacc[nf][3] *= sc1;
        }
        {
            int vrow = lane & 15, vcol = (lane >> 4) * 8;
#pragma unroll
            for (int ks = 0; ks < 4; ks++) {
                uint32_t ah[4];
                ah[0] = pack_f16(sf[2*ks][0],   sf[2*ks][1]);
                ah[1] = pack_f16(sf[2*ks][2],   sf[2*ks][3]);
                ah[2] = pack_f16(sf[2*ks+1][0], sf[2*ks+1][1]);
                ah[3] = pack_f16(sf[2*ks+1][2], sf[2*ks+1][3]);
#pragma unroll
                for (int df = 0; df < 4; df++) {
                    uint32_t v4[4];
                    uint32_t ad = sb + A_SV + st
                        + (uint32_t)(ks*16 + vrow) * A_PITCH + (df*16 + vcol) * 2;
                    ldm_x4_t(v4, ad);
                    mma_f16(oacc[2*df],     ah, v4[0], v4[1]);
                    mma_f16(oacc[2*df + 1], ah, v4[2], v4[3]);
                }
            }
        }
        __syncthreads();
    }

    float* ost = (float*)(sm + A_SK);
#pragma unroll
    for (int nf = 0; nf < 8; nf++) {
        int c = nf*8 + cq;
        ost[(m0 + r_l) * 72 + c]         = oacc[nf][0];
        ost[(m0 + r_l) * 72 + c + 1]     = oacc[nf][1];
        ost[(m0 + r_l + 8) * 72 + c]     = oacc[nf][2];
        ost[(m0 + r_l + 8) * 72 + c + 1] = oacc[nf][3];
    }
    if ((lane & 3) == 0) {
        ((float*)(sm + A_SMS))[m0 + r_l]     = mi0;
        ((float*)(sm + A_SMS))[m0 + r_l + 8] = mi1;
        ((float*)(sm + A_SLS))[m0 + r_l]     = li0;
        ((float*)(sm + A_SLS))[m0 + r_l + 8] = li1;
    }
    __syncthreads();

    {
        int m = tid >> 1, hf = tid & 1;
        int i = qb*64 + m;
        const __half2* q2 = (const __half2*)(Qf + (size_t)i * Dm + h*64);
        const __half2* k2 = (const __half2*)(Kf + (size_t)(S + i) * Dm + h*64);
        float dot = 0.f;
#pragma unroll
        for (int t = 0; t < 32; t++) {
            float2 qa = __half22float2(q2[t]);
            float2 ka = __half22float2(k2[t]);
            dot += qa.x * ka.x + qa.y * ka.y;
        }
        float ssf = dot;
        float mi = ((float*)(sm + A_SMS))[m];
        float li = ((float*)(sm + A_SLS))[m];
        float nm = fmaxf(mi, ssf);
        float sc = __expf(mi - nm);
        float pp = __expf(ssf - nm);
        float inv = 1.f / (li * sc + pp);
        const __half2* v2 = (const __half2*)(Vf + (size_t)(S + i) * Dm + h*64 + hf*32);
        float* orow = ost + m*72 + hf*32;
        uint32_t hh[8];
#pragma unroll
        for (int t = 0; t < 16; t++) {
            float2 va = __half22float2(v2[t]);
            float val0 = (orow[t*2]   * sc + pp * va.x) * inv;
            float val1 = (orow[t*2+1] * sc + pp * va.y) * inv;
            hh[t & 7] = pack_f16(val0, val1);
            if ((t & 7) == 7) {
                int t8 = t >> 3;
                *(uint4*)(O + (size_t)i * Dm + h*64 + hf*32 + t8*16)     = *(uint4*)(hh);
                *(uint4*)(O + (size_t)i * Dm + h*64 + hf*32 + t8*16 + 8) = *(uint4*)(hh + 4);
            }
        }
    }
}

// ------------- launch -------------
extern "C" void kernel_launch(void* const* d_in, const int* in_sizes, int n_in,
                              void* d_out, int out_size)
{
    const float* hidden = (const float*)d_in[0];
    const float* memory = (const float*)d_in[1];
    const float* ln1w = (const float*)d_in[4];
    const float* ln1b = (const float*)d_in[5];
    const float* ln2w = (const float*)d_in[6];
    const float* ln2b = (const float*)d_in[7];
    const float* Wq = (const float*)d_in[8];
    const float* Wk = (const float*)d_in[9];
    const float* Wv = (const float*)d_in[10];
    const float* Wo = (const float*)d_in[11];
    const float* Wg = (const float*)d_in[12];
    const float* Wu = (const float*)d_in[13];
    const float* Wd = (const float*)d_in[14];
    float* out = (float*)d_out;

    void* p;
    cudaGetSymbolAddress(&p, g_x);   __half* x = (__half*)p;
    cudaGetSymbolAddress(&p, g_q);   __half* q = (__half*)p;
    cudaGetSymbolAddress(&p, g_k);   __half* k = (__half*)p;
    cudaGetSymbolAddress(&p, g_v);   __half* v = (__half*)p;
    cudaGetSymbolAddress(&p, g_a);   __half* a = (__half*)p;
    cudaGetSymbolAddress(&p, g_h);   float* hbuf = (float*)p;
    cudaGetSymbolAddress(&p, g_h2);  __half* h2 = (__half*)p;
    cudaGetSymbolAddress(&p, g_gt);  __half* gt = (__half*)p;
    cudaGetSymbolAddress(&p, g_g);   __half* gbuf = (__half*)p;
    cudaGetSymbolAddress(&p, g_wq);  __half* wq = (__half*)p;
    cudaGetSymbolAddress(&p, g_wk);  __half* wk = (__half*)p;
    cudaGetSymbolAddress(&p, g_wv);  __half* wv = (__half*)p;
    cudaGetSymbolAddress(&p, g_wo);  __half* wo = (__half*)p;
    cudaGetSymbolAddress(&p, g_wg);  __half* wg = (__half*)p;
    cudaGetSymbolAddress(&p, g_wu);  __half* wu = (__half*)p;
    cudaGetSymbolAddress(&p, g_wd);  __half* wd = (__half*)p;

    cudaFuncSetAttribute(gemm1<0>, cudaFuncAttributeMaxDynamicSharedMemorySize, G_DSMEM);
    cudaFuncSetAttribute(gemm1<4>, cudaFuncAttributeMaxDynamicSharedMemorySize, G_DSMEM);
    cudaFuncSetAttribute(gemm1<7>, cudaFuncAttributeMaxDynamicSharedMemorySize, G_DSMEM);
    cudaFuncSetAttribute(gemm1<8>, cudaFuncAttributeMaxDynamicSharedMemorySize, G_DSMEM);
    cudaFuncSetAttribute(attn_mma_kernel, cudaFuncAttributeMaxDynamicSharedMemorySize, A_DSMEM);

    ln_conv_kernel<<<S, 256>>>(memory, ln1w, ln1b, x);
    ln_conv_kernel<<<S, 256>>>(hidden, ln1w, ln1b, x + (size_t)S * Dm);

    conv_all_kernel<<<16384, 256>>>(Wq, Wk, Wv, Wo, Wg, Wu, Wd,
                                    wq, wk, wv, wo, wg, wu, wd);

    {
        dim3 gKV(32, L / 128);
        gemm1<7><<<gKV, 128, G_DSMEM>>>(x, wk, wv, nullptr, nullptr, k, v,
                                        1.0f, L, Dm, Dm, 16);
        dim3 gQ(16, S / 128);
        gemm1<4><<<gQ, 128, G_DSMEM>>>(x + (size_t)S * Dm, wq, nullptr, nullptr, nullptr,
                                       q, nullptr, 0.125f, S, Dm, Dm, 0);
    }

    {
        dim3 g(S / 64, NH);
        attn_mma_kernel<<<g, 128, A_DSMEM>>>(q, k, v, a);
    }

    {
        dim3 g(Dm / 128, S / 128);
        gemm1<0><<<g, 128, G_DSMEM>>>(a, wo, nullptr, hidden, hbuf, nullptr, nullptr,
                                      1.0f, S, Dm, Dm, 0);
    }
    ln_conv_kernel<<<S, 256>>>(hbuf, ln2w, ln2b, h2);
    {
        dim3 g(128, S / 128);
        gemm1<8><<<g, 128, G_DSMEM>>>(h2, wg, wu, nullptr, nullptr, gt, gbuf,
                                      1.0f, S, FF, Dm, 64);
        mul_kernel<<<S * FF / 2048, 256>>>(gbuf, gt, S * FF / 8);
    }
    {
        dim3 g(Dm / 128, S / 128);
        gemm1<0><<<g, 128, G_DSMEM>>>(gbuf, wd, nullptr, hbuf, out, nullptr, nullptr,
                                      1.0f, S, Dm, FF, 0);
    }
}

// round 16
// speedup vs baseline: 1.3911x; 1.0017x over previous
#include <cuda_runtime.h>
#include <cuda_fp16.h>
#include <cstdint>

#define S    2048
#define Dm   2048
#define FF   8192
#define NH   32
#define HD   64
#define L    4096

__device__ __forceinline__ uint32_t smem_u32(const void* p) {
    uint32_t a;
    asm("{ .reg .u64 t; cvta.to.shared.u64 t, %1; cvt.u32.u64 %0, t; }" : "=r"(a) : "l"(p));
    return a;
}
__device__ __forceinline__ void ldm_x4(uint32_t* r, uint32_t a) {
    asm volatile("ldmatrix.sync.aligned.m8n8.x4.shared.b16 {%0,%1,%2,%3}, [%4];"
        : "=r"(r[0]), "=r"(r[1]), "=r"(r[2]), "=r"(r[3]) : "r"(a));
}
__device__ __forceinline__ void ldm_x4_t(uint32_t* r, uint32_t a) {
    asm volatile("ldmatrix.sync.aligned.m8n8.x4.trans.shared.b16 {%0,%1,%2,%3}, [%4];"
        : "=r"(r[0]), "=r"(r[1]), "=r"(r[2]), "=r"(r[3]) : "r"(a));
}
__device__ __forceinline__ void mma_f16(float* c, const uint32_t* a, uint32_t b0, uint32_t b1) {
    asm volatile("mma.sync.aligned.m16n8k16.row.col.f32.f16.f16.f32 "
        "{%0,%1,%2,%3}, {%4,%5,%6,%7}, {%8,%9}, {%0,%1,%2,%3};"
        : "+f"(c[0]), "+f"(c[1]), "+f"(c[2]), "+f"(c[3])
        : "r"(a[0]), "r"(a[1]), "r"(a[2]), "r"(a[3]), "r"(b0), "r"(b1));
}
__device__ __forceinline__ uint32_t pack_f16(float a, float b) {
    __half2 t; t.x = __float2half_rn(a); t.y = __float2half_rn(b);
    return *(uint32_t*)&t;
}
#define CP_ASYNC16(dst, src) \
    asm volatile("cp.async.cg.shared.global [%0], [%1], 16;" :: "r"(dst), "l"(src))
#define CP_COMMIT() asm volatile("cp.async.commit_group;" ::: "memory")
#define CP_WAIT1()  asm volatile("cp.async.wait_group 1;" ::: "memory")
#define CP_WAIT2()  asm volatile("cp.async.wait_group 2;" ::: "memory")

// ------------- scratch -------------
__device__ __half g_x  [L * Dm];
__device__ __half g_q  [S * Dm];
__device__ __half g_k  [L * Dm];
__device__ __half g_v  [L * Dm];
__device__ __half g_a  [S * Dm];
__device__ float  g_h  [S * Dm];
__device__ __half g_h2 [S * Dm];
__device__ __half g_gt [S * FF];
__device__ __half g_g  [S * FF];
__device__ __half g_wq[Dm * Dm];
__device__ __half g_wk[Dm * Dm];
__device__ __half g_wv[Dm * Dm];
__device__ __half g_wo[Dm * Dm];
__device__ __half g_wg[FF * Dm];
__device__ __half g_wu[FF * Dm];
__device__ __half g_wd[Dm * FF];

// ------------- merged fp32 -> fp16 convert of all 7 weights -------------
__global__ __launch_bounds__(256) void conv_all_kernel(
    const float* __restrict__ Wq, const float* __restrict__ Wk,
    const float* __restrict__ Wv, const float* __restrict__ Wo,
    const float* __restrict__ Wg, const float* __restrict__ Wu,
    const float* __restrict__ Wd,
    __half* __restrict__ wq, __half* __restrict__ wk, __half* __restrict__ wv,
    __half* __restrict__ wo, __half* __restrict__ wg, __half* __restrict__ wu,
    __half* __restrict__ wd)
{
    int b = blockIdx.x;
    const float* src; __half* dst; int rel;
    if      (b < 1024)  { src = Wq; dst = wq; rel = b; }
    else if (b < 2048)  { src = Wk; dst = wk; rel = b - 1024; }
    else if (b < 3072)  { src = Wv; dst = wv; rel = b - 2048; }
    else if (b < 4096)  { src = Wo; dst = wo; rel = b - 3072; }
    else if (b < 8192)  { src = Wg; dst = wg; rel = b - 4096; }
    else if (b < 12288) { src = Wu; dst = wu; rel = b - 8192; }
    else                { src = Wd; dst = wd; rel = b - 12288; }
    int base = rel * 1024 + threadIdx.x;
#pragma unroll
    for (int t = 0; t < 4; t++) {
        float4 x = ((const float4*)src)[base + t * 256];
        uint2 o; o.x = pack_f16(x.x, x.y); o.y = pack_f16(x.z, x.w);
        ((uint2*)dst)[base + t * 256] = o;
    }
}

// ------------- silu(gate) * up elementwise (fp16) -------------
__global__ __launch_bounds__(256) void mul_kernel(
    __half* __restrict__ G, const __half* __restrict__ T, int n8)
{
    int i = blockIdx.x * blockDim.x + threadIdx.x;
    if (i >= n8) return;
    uint4 a = ((const uint4*)G)[i];
    uint4 b = ((const uint4*)T)[i];
    __half2* ah = (__half2*)&a;
    __half2* bh = (__half2*)&b;
#pragma unroll
    for (int t = 0; t < 4; t++) ah[t] = __hmul2(ah[t], bh[t]);
    ((uint4*)G)[i] = a;
}

// ------------- LayerNorm -> single fp16 -------------
__global__ __launch_bounds__(256) void ln_conv_kernel(
    const float* __restrict__ X, const float* __restrict__ w,
    const float* __restrict__ b, __half* __restrict__ O)
{
    int row = blockIdx.x, tid = threadIdx.x;
    const float* xr = X + (size_t)row * Dm;
    float4 a = ((const float4*)xr)[tid * 2];
    float4 c = ((const float4*)xr)[tid * 2 + 1];
    float s  = a.x + a.y + a.z + a.w + c.x + c.y + c.z + c.w;
    float ss = a.x*a.x + a.y*a.y + a.z*a.z + a.w*a.w
             + c.x*c.x + c.y*c.y + c.z*c.z + c.w*c.w;
#pragma unroll
    for (int o = 16; o; o >>= 1) {
        s  += __shfl_xor_sync(0xffffffffu, s,  o);
        ss += __shfl_xor_sync(0xffffffffu, ss, o);
    }
    __shared__ float bs[8], bss[8];
    if ((tid & 31) == 0) { bs[tid >> 5] = s; bss[tid >> 5] = ss; }
    __syncthreads();
    float ts = 0.f, tss = 0.f;
#pragma unroll
    for (int i = 0; i < 8; i++) { ts += bs[i]; tss += bss[i]; }
    float mean = ts * (1.f / Dm);
    float inv  = rsqrtf(tss * (1.f / Dm) - mean * mean + 1e-5f);
    int d = tid * 8;
    float4 w0 = ((const float4*)w)[tid*2], w1 = ((const float4*)w)[tid*2+1];
    float4 b0 = ((const float4*)b)[tid*2], b1 = ((const float4*)b)[tid*2+1];
    float v8[8];
    v8[0]=(a.x-mean)*inv*w0.x+b0.x; v8[1]=(a.y-mean)*inv*w0.y+b0.y;
    v8[2]=(a.z-mean)*inv*w0.z+b0.z; v8[3]=(a.w-mean)*inv*w0.w+b0.w;
    v8[4]=(c.x-mean)*inv*w1.x+b1.x; v8[5]=(c.y-mean)*inv*w1.y+b1.y;
    v8[6]=(c.z-mean)*inv*w1.z+b1.z; v8[7]=(c.w-mean)*inv*w1.w+b1.w;
    uint4 o;
    o.x = pack_f16(v8[0], v8[1]); o.y = pack_f16(v8[2], v8[3]);
    o.z = pack_f16(v8[4], v8[5]); o.w = pack_f16(v8[6], v8[7]);
    *(uint4*)(O + (size_t)row * Dm + d) = o;
}

// ------------- GEMM: fp16, 128x128 CTA, 4 warps x 64x64, GBK=32, batched frags -------------
// MODE 0: fp32 (+Res) | 4: rope+scale -> fp16 (Q)
// MODE 7: bx<nsplit -> rope->OH (K) ; else plain->O2 (V, weights B2)
// MODE 8: bx<nsplit -> silu->OH (gate) ; else plain->O2 (up, weights B2)
#define GBK 32
#define G_ROWB 80
#define G_TILEB (128 * G_ROWB)            // 10240
#define G_STAGEB (2 * G_TILEB)            // 20480
#define G_NST 4
#define G_DSMEM (G_NST * G_STAGEB)        // 81920

template<int MODE>
__global__ __launch_bounds__(128, 2)
void gemm1(const __half* __restrict__ A, const __half* __restrict__ B,
           const __half* __restrict__ B2, const float* __restrict__ Res,
           float* __restrict__ C, __half* __restrict__ OH,
           __half* __restrict__ O2, float scale, int M, int N, int K, int nsplit)
{
    extern __shared__ char smem[];
    uint32_t sb = smem_u32(smem);
    int tid  = threadIdx.x, wid = tid >> 5, lane = tid & 31;
    int wm = wid & 1, wn = wid >> 1;
    int bm = blockIdx.y * 128;
    int bx = blockIdx.x;
    const __half* Bp = B;
    bool first = true;
    if ((MODE == 7 || MODE == 8) && bx >= nsplit) { first = false; Bp = B2; bx -= nsplit; }
    int bn = bx * 128;

    auto loadChunk = [&](int stg, int k0) {
        uint32_t base = sb + stg * G_STAGEB;
#pragma unroll
        for (int i = 0; i < 4; i++) {
            int idx = tid + i * 128;
            int r = idx >> 2, c = idx & 3;
            uint32_t doff = r * G_ROWB + c * 16;
            size_t soff = (size_t)r * K + k0 + c * 8;
            CP_ASYNC16(base + doff,           A  + (size_t)bm * K + soff);
            CP_ASYNC16(base + G_TILEB + doff, Bp + (size_t)bn * K + soff);
        }
    };

    float acc[4][8][4];
#pragma unroll
    for (int i = 0; i < 4; i++)
#pragma unroll
        for (int j = 0; j < 8; j++)
#pragma unroll
            for (int t = 0; t < 4; t++) acc[i][j][t] = 0.f;

    int NKC = K / GBK;
    loadChunk(0, 0);        CP_COMMIT();
    loadChunk(1, GBK);      CP_COMMIT();
    loadChunk(2, 2 * GBK);  CP_COMMIT();

    int a_row = lane & 15;
    int a_kb  = (lane >> 4) * 16;
    int b_row = lane & 7;
    int b_kb  = ((lane >> 3) & 1) * 16;
    int nsel  = (lane >> 4) & 1;

    uint32_t Af[2][4][4], Bf[2][8][2];

    for (int k = 0; k < NKC; k++) {
        int stg = k & (G_NST - 1);
        CP_WAIT2();
        __syncthreads();
        if (k + 3 < NKC) { loadChunk((k + 3) & (G_NST - 1), (k + 3) * GBK); }
        CP_COMMIT();
        uint32_t base = sb + stg * G_STAGEB;
        // Batch ALL fragment loads (both kk halves) before any MMA: 24 independent ldmatrix
#pragma unroll
        for (int kk = 0; kk < 2; kk++) {
#pragma unroll
            for (int mf = 0; mf < 4; mf++) {
                uint32_t addr = base + (uint32_t)((wm*64 + mf*16 + a_row) * G_ROWB)
                              + kk*32 + a_kb;
                ldm_x4(Af[kk][mf], addr);
            }
#pragma unroll
            for (int g = 0; g < 2; g++)
#pragma unroll
                for (int p = 0; p < 2; p++) {
                    uint32_t addr = base + G_TILEB
                        + (uint32_t)((wn*64 + (g*4 + p*2 + nsel)*8 + b_row) * G_ROWB)
                        + kk*32 + b_kb;
                    uint32_t r4[4];
                    ldm_x4(r4, addr);
                    int f = g*4 + p*2;
                    Bf[kk][f][0]   = r4[0]; Bf[kk][f][1]   = r4[1];
                    Bf[kk][f+1][0] = r4[2]; Bf[kk][f+1][1] = r4[3];
                }
        }
#pragma unroll
        for (int kk = 0; kk < 2; kk++)
#pragma unroll
            for (int mf = 0; mf < 4; mf++)
#pragma unroll
                for (int nf = 0; nf < 8; nf++)
                    mma_f16(acc[mf][nf], Af[kk][mf], Bf[kk][nf][0], Bf[kk][nf][1]);
    }

    int rr = lane >> 2, cp = lane & 3;
    if (MODE == 4 || (MODE == 7 && first)) {
#pragma unroll
        for (int mf = 0; mf < 4; mf++)
#pragma unroll
            for (int j = 0; j < 4; j++) {
                int d = cp * 2 + (j & 1);
                int row = bm + wm*64 + mf*16 + rr + ((j >> 1) * 8);
                int pos = row & (S - 1);
                float invf = __powf(10000.f, -(float)d * 0.125f);
                float sn, cs; sincosf(pos * invf, &sn, &cs);
                float x1 = acc[mf][0][j], x2 = acc[mf][1][j];
                acc[mf][0][j] = x1 * cs - x2 * sn;
                acc[mf][1][j] = x2 * cs + x1 * sn;
            }
    }
#pragma unroll
    for (int mf = 0; mf < 4; mf++) {
        int row0 = bm + wm*64 + mf*16 + rr;
#pragma unroll
        for (int nf = 0; nf < 8; nf++) {
            int col = bn + wn*64 + nf*8 + cp*2;
            float* c = acc[mf][nf];
            size_t o0 = (size_t)row0 * N + col;
            size_t o1 = (size_t)(row0 + 8) * N + col;
            if (MODE == 0) {
                float2 v0 = make_float2(c[0], c[1]);
                float2 v1 = make_float2(c[2], c[3]);
                if (Res) {
                    float2 e0 = *(const float2*)(Res + o0);
                    float2 e1 = *(const float2*)(Res + o1);
                    v0.x += e0.x; v0.y += e0.y; v1.x += e1.x; v1.y += e1.y;
                }
                *(float2*)(C + o0) = v0;
                *(float2*)(C + o1) = v1;
            } else if (MODE == 4) {
                *(uint32_t*)(OH + o0) = pack_f16(c[0] * scale, c[1] * scale);
                *(uint32_t*)(OH + o1) = pack_f16(c[2] * scale, c[3] * scale);
            } else if (MODE == 7) {
                __half* Op = first ? OH : O2;
                *(uint32_t*)(Op + o0) = pack_f16(c[0], c[1]);
                *(uint32_t*)(Op + o1) = pack_f16(c[2], c[3]);
            } else if (MODE == 8) {
                if (first) {
                    float v0 = c[0] / (1.f + __expf(-c[0]));
                    float v1 = c[1] / (1.f + __expf(-c[1]));
                    float v2 = c[2] / (1.f + __expf(-c[2]));
                    float v3 = c[3] / (1.f + __expf(-c[3]));
                    *(uint32_t*)(OH + o0) = pack_f16(v0, v1);
                    *(uint32_t*)(OH + o1) = pack_f16(v2, v3);
                } else {
                    *(uint32_t*)(O2 + o0) = pack_f16(c[0], c[1]);
                    *(uint32_t*)(O2 + o1) = pack_f16(c[2], c[3]);
                }
            }
        }
    }
}

// ------------- flash attention: fully 1-term fp16, heavy-first -------------
#define A_PITCH 144
#define A_SQ  0u
#define A_SK  9216u
#define A_SV  27648u
#define A_SMS 46080u
#define A_SLS 46336u
#define A_DSMEM 46592

__global__ __launch_bounds__(128, 2)
void attn_mma_kernel(const __half* __restrict__ Qf, const __half* __restrict__ Kf,
                     const __half* __restrict__ Vf, __half* __restrict__ O)
{
    extern __shared__ char sm[];
    uint32_t sb = smem_u32(sm);
    const int qb = gridDim.x - 1 - blockIdx.x;
    const int h = blockIdx.y;
    const int tid = threadIdx.x, wid = tid >> 5, lane = tid & 31;
    const int m0 = wid * 16;

#pragma unroll
    for (int j = 0; j < 4; j++) {
        int idx = tid + j * 128;
        int row = idx >> 3, c = idx & 7;
        size_t g = (size_t)(qb*64 + row) * Dm + h*64 + c*8;
        *(uint4*)(sm + A_SQ + row*A_PITCH + c*16) = *(const uint4*)(Qf + g);
    }
    auto loadKV = [&](int kb, int st) {
        uint32_t o = (uint32_t)st * 9216u;
#pragma unroll
        for (int j = 0; j < 4; j++) {
            int idx = tid + j * 128;
            int row = idx >> 3, c = idx & 7;
            size_t g = (size_t)(kb*64 + row) * Dm + h*64 + c*8;
            uint32_t d = o + row*A_PITCH + c*16;
            CP_ASYNC16(sb + A_SK + d, Kf + g);
            CP_ASYNC16(sb + A_SV + d, Vf + g);
        }
    };
    loadKV(0, 0); CP_COMMIT();
    __syncthreads();

    uint32_t qf[4][4];
    {
        int a_row = lane & 15, koff = (lane >> 4) * 16;
#pragma unroll
        for (int kk = 0; kk < 4; kk++) {
            uint32_t ad = sb + A_SQ + (uint32_t)(m0 + a_row) * A_PITCH + kk*32 + koff;
            ldm_x4(qf[kk], ad);
        }
    }

    float oacc[8][4];
#pragma unroll
    for (int nf = 0; nf < 8; nf++)
#pragma unroll
        for (int t = 0; t < 4; t++) oacc[nf][t] = 0.f;
    float mi0 = -1e30f, mi1 = -1e30f, li0 = 0.f, li1 = 0.f;
    const int r_l = lane >> 2, cq = (lane & 3) * 2;

    for (int kb = 0; kb <= qb; kb++) {
        if (kb < qb) loadKV(kb + 1, (kb + 1) & 1);
        CP_COMMIT();
        CP_WAIT1();
        __syncthreads();
        uint32_t st = (uint32_t)(kb & 1) * 9216u;

        float sf[8][4];
#pragma unroll
        for (int nf = 0; nf < 8; nf++)
#pragma unroll
            for (int t = 0; t < 4; t++) sf[nf][t] = 0.f;
        {
            int b_row = lane & 7, b_kb = ((lane >> 3) & 1) * 16, nsel = (lane >> 4) & 1;
#pragma unroll
            for (int kk = 0; kk < 4; kk++) {
                uint32_t bh[8][2];
#pragma unroll
                for (int g = 0; g < 2; g++)
#pragma unroll
                    for (int p = 0; p < 2; p++) {
                        uint32_t ad = sb + A_SK + st
                            + (uint32_t)(((g*4 + p*2 + nsel)*8 + b_row)) * A_PITCH
                            + kk*32 + b_kb;
                        uint32_t r4[4];
                        ldm_x4(r4, ad);
                        int f = g*4 + p*2;
                        bh[f][0] = r4[0]; bh[f][1] = r4[1];
                        bh[f+1][0] = r4[2]; bh[f+1][1] = r4[3];
                    }
#pragma unroll
                for (int nf = 0; nf < 8; nf++) mma_f16(sf[nf], qf[kk], bh[nf][0], bh[nf][1]);
            }
        }
        if (kb == qb) {
#pragma unroll
            for (int nf = 0; nf < 8; nf++)
#pragma unroll
                for (int hh = 0; hh < 2; hh++) {
                    int jl = nf*8 + cq + hh;
                    if (jl >= m0 + r_l)     sf[nf][hh]     = -1e30f;
                    if (jl >= m0 + r_l + 8) sf[nf][2 + hh] = -1e30f;
                }
        }
        float mx0 = -1e30f, mx1 = -1e30f;
#pragma unroll
        for (int nf = 0; nf < 8; nf++) {
            mx0 = fmaxf(mx0, fmaxf(sf[nf][0], sf[nf][1]));
            mx1 = fmaxf(mx1, fmaxf(sf[nf][2], sf[nf][3]));
        }
        mx0 = fmaxf(mx0, __shfl_xor_sync(0xffffffffu, mx0, 1));
        mx0 = fmaxf(mx0, __shfl_xor_sync(0xffffffffu, mx0, 2));
        mx1 = fmaxf(mx1, __shfl_xor_sync(0xffffffffu, mx1, 1));
        mx1 = fmaxf(mx1, __shfl_xor_sync(0xffffffffu, mx1, 2));
        float nm0 = fmaxf(mi0, mx0), nm1 = fmaxf(mi1, mx1);
        float sc0 = __expf(mi0 - nm0), sc1 = __expf(mi1 - nm1);
        float sum0 = 0.f, sum1 = 0.f;
#pragma unroll
        for (int nf = 0; nf < 8; nf++) {
            sf[nf][0] = (sf[nf][0] <= -1e29f) ? 0.f : __expf(sf[nf][0] - nm0); sum0 += sf[nf][0];
            sf[nf][1] = (sf[nf][1] <= -1e29f) ? 0.f : __expf(sf[nf][1] - nm0); sum0 += sf[nf][1];
            sf[nf][2] = (sf[nf][2] <= -1e29f) ? 0.f : __expf(sf[nf][2] - nm1); sum1 += sf[nf][2];
            sf[nf][3] = (sf[nf][3] <= -1e29f) ? 0.f : __expf(sf[nf][3] - nm1); sum1 += sf[nf][3];
        }
        sum0 += __shfl_xor_sync(0xffffffffu, sum0, 1);
        sum0 += __shfl_xor_sync(0xffffffffu, sum0, 2);
        sum1 += __shfl_xor_sync(0xffffffffu, sum1, 1);
        sum1 += __shfl_xor_sync(0xffffffffu, sum1, 2);
        li0 = li0 * sc0 + sum0; li1 = li1 * sc1 + sum1;
        mi0 = nm0; mi1 = nm1;
#pragma unroll
        for (int nf = 0; nf < 8; nf++) {
            oacc[nf][0] *= sc0; oacc[nf][1] *= sc0;
            oacc[nf][2] *= sc1; oacc[nf][3] *= sc1;
        }
        {
            int vrow = lane & 15, vcol = (lane >> 4) * 8;
#pragma unroll
            for (int ks = 0; ks < 4; ks++) {
                uint32_t ah[4];
                ah[0] = pack_f16(sf[2*ks][0],   sf[2*ks][1]);
                ah[1] = pack_f16(sf[2*ks][2],   sf[2*ks][3]);
                ah[2] = pack_f16(sf[2*ks+1][0], sf[2*ks+1][1]);
                ah[3] = pack_f16(sf[2*ks+1][2], sf[2*ks+1][3]);
#pragma unroll
                for (int df = 0; df < 4; df++) {
                    uint32_t v4[4];
                    uint32_t ad = sb + A_SV + st
                        + (uint32_t)(ks*16 + vrow) * A_PITCH + (df*16 + vcol) * 2;
                    ldm_x4_t(v4, ad);
                    mma_f16(oacc[2*df],     ah, v4[0], v4[1]);
                    mma_f16(oacc[2*df + 1], ah, v4[2], v4[3]);
                }
            }
        }
        __syncthreads();
    }

    float* ost = (float*)(sm + A_SK);
#pragma unroll
    for (int nf = 0; nf < 8; nf++) {
        int c = nf*8 + cq;
        ost[(m0 + r_l) * 72 + c]         = oacc[nf][0];
        ost[(m0 + r_l) * 72 + c + 1]     = oacc[nf][1];
        ost[(m0 + r_l + 8) * 72 + c]     = oacc[nf][2];
        ost[(m0 + r_l + 8) * 72 + c + 1] = oacc[nf][3];
    }
    if ((lane & 3) == 0) {
        ((float*)(sm + A_SMS))[m0 + r_l]     = mi0;
        ((float*)(sm + A_SMS))[m0 + r_l + 8] = mi1;
        ((float*)(sm + A_SLS))[m0 + r_l]     = li0;
        ((float*)(sm + A_SLS))[m0 + r_l + 8] = li1;
    }
    __syncthreads();

    {
        int m = tid >> 1, hf = tid & 1;
        int i = qb*64 + m;
        const __half2* q2 = (const __half2*)(Qf + (size_t)i * Dm + h*64);
        const __half2* k2 = (const __half2*)(Kf + (size_t)(S + i) * Dm + h*64);
        float dot = 0.f;
#pragma unroll
        for (int t = 0; t < 32; t++) {
            float2 qa = __half22float2(q2[t]);
            float2 ka = __half22float2(k2[t]);
            dot += qa.x * ka.x + qa.y * ka.y;
        }
        float ssf = dot;
        float mi = ((float*)(sm + A_SMS))[m];
        float li = ((float*)(sm + A_SLS))[m];
        float nm = fmaxf(mi, ssf);
        float sc = __expf(mi - nm);
        float pp = __expf(ssf - nm);
        float inv = 1.f / (li * sc + pp);
        const __half2* v2 = (const __half2*)(Vf + (size_t)(S + i) * Dm + h*64 + hf*32);
        float* orow = ost + m*72 + hf*32;
        uint32_t hh[8];
#pragma unroll
        for (int t = 0; t < 16; t++) {
            float2 va = __half22float2(v2[t]);
            float val0 = (orow[t*2]   * sc + pp * va.x) * inv;
            float val1 = (orow[t*2+1] * sc + pp * va.y) * inv;
            hh[t & 7] = pack_f16(val0, val1);
            if ((t & 7) == 7) {
                int t8 = t >> 3;
                *(uint4*)(O + (size_t)i * Dm + h*64 + hf*32 + t8*16)     = *(uint4*)(hh);
                *(uint4*)(O + (size_t)i * Dm + h*64 + hf*32 + t8*16 + 8) = *(uint4*)(hh + 4);
            }
        }
    }
}

// ------------- launch -------------
extern "C" void kernel_launch(void* const* d_in, const int* in_sizes, int n_in,
                              void* d_out, int out_size)
{
    const float* hidden = (const float*)d_in[0];
    const float* memory = (const float*)d_in[1];
    const float* ln1w = (const float*)d_in[4];
    const float* ln1b = (const float*)d_in[5];
    const float* ln2w = (const float*)d_in[6];
    const float* ln2b = (const float*)d_in[7];
    const float* Wq = (const float*)d_in[8];
    const float* Wk = (const float*)d_in[9];
    const float* Wv = (const float*)d_in[10];
    const float* Wo = (const float*)d_in[11];
    const float* Wg = (const float*)d_in[12];
    const float* Wu = (const float*)d_in[13];
    const float* Wd = (const float*)d_in[14];
    float* out = (float*)d_out;

    void* p;
    cudaGetSymbolAddress(&p, g_x);   __half* x = (__half*)p;
    cudaGetSymbolAddress(&p, g_q);   __half* q = (__half*)p;
    cudaGetSymbolAddress(&p, g_k);   __half* k = (__half*)p;
    cudaGetSymbolAddress(&p, g_v);   __half* v = (__half*)p;
    cudaGetSymbolAddress(&p, g_a);   __half* a = (__half*)p;
    cudaGetSymbolAddress(&p, g_h);   float* hbuf = (float*)p;
    cudaGetSymbolAddress(&p, g_h2);  __half* h2 = (__half*)p;
    cudaGetSymbolAddress(&p, g_gt);  __half* gt = (__half*)p;
    cudaGetSymbolAddress(&p, g_g);   __half* gbuf = (__half*)p;
    cudaGetSymbolAddress(&p, g_wq);  __half* wq = (__half*)p;
    cudaGetSymbolAddress(&p, g_wk);  __half* wk = (__half*)p;
    cudaGetSymbolAddress(&p, g_wv);  __half* wv = (__half*)p;
    cudaGetSymbolAddress(&p, g_wo);  __half* wo = (__half*)p;
    cudaGetSymbolAddress(&p, g_wg);  __half* wg = (__half*)p;
    cudaGetSymbolAddress(&p, g_wu);  __half* wu = (__half*)p;
    cudaGetSymbolAddress(&p, g_wd);  __half* wd = (__half*)p;

    cudaFuncSetAttribute(gemm1<0>, cudaFuncAttributeMaxDynamicSharedMemorySize, G_DSMEM);
    cudaFuncSetAttribute(gemm1<4>, cudaFuncAttributeMaxDynamicSharedMemorySize, G_DSMEM);
    cudaFuncSetAttribute(gemm1<7>, cudaFuncAttributeMaxDynamicSharedMemorySize, G_DSMEM);
    cudaFuncSetAttribute(gemm1<8>, cudaFuncAttributeMaxDynamicSharedMemorySize, G_DSMEM);
    cudaFuncSetAttribute(attn_mma_kernel, cudaFuncAttributeMaxDynamicSharedMemorySize, A_DSMEM);

    ln_conv_kernel<<<S, 256>>>(memory, ln1w, ln1b, x);
    ln_conv_kernel<<<S, 256>>>(hidden, ln1w, ln1b, x + (size_t)S * Dm);

    conv_all_kernel<<<16384, 256>>>(Wq, Wk, Wv, Wo, Wg, Wu, Wd,
                                    wq, wk, wv, wo, wg, wu, wd);

    {
        dim3 gKV(32, L / 128);
        gemm1<7><<<gKV, 128, G_DSMEM>>>(x, wk, wv, nullptr, nullptr, k, v,
                                        1.0f, L, Dm, Dm, 16);
        dim3 gQ(16, S / 128);
        gemm1<4><<<gQ, 128, G_DSMEM>>>(x + (size_t)S * Dm, wq, nullptr, nullptr, nullptr,
                                       q, nullptr, 0.125f, S, Dm, Dm, 0);
    }

    {
        dim3 g(S / 64, NH);
        attn_mma_kernel<<<g, 128, A_DSMEM>>>(q, k, v, a);
    }

    {
        dim3 g(Dm / 128, S / 128);
        gemm1<0><<<g, 128, G_DSMEM>>>(a, wo, nullptr, hidden, hbuf, nullptr, nullptr,
                                      1.0f, S, Dm, Dm, 0);
    }
    ln_conv_kernel<<<S, 256>>>(hbuf, ln2w, ln2b, h2);
    {
        dim3 g(128, S / 128);
        gemm1<8><<<g, 128, G_DSMEM>>>(h2, wg, wu, nullptr, nullptr, gt, gbuf,
                                      1.0f, S, FF, Dm, 64);
        mul_kernel<<<S * FF / 2048, 256>>>(gbuf, gt, S * FF / 8);
    }
    {
        dim3 g(Dm / 128, S / 128);
        gemm1<0><<<g, 128, G_DSMEM>>>(gbuf, wd, nullptr, hbuf, out, nullptr, nullptr,
                                      1.0f, S, Dm, FF, 0);
    }
}